// round 4
// baseline (speedup 1.0000x reference)
#include <cuda_runtime.h>
#include <math.h>

#define LSEQ   4096
#define DCH    768
#define NBATCH 8
#define NBLK   8
#define BS     96
#define NMODES 2049   // LSEQ/2 + 1
#define MP     2064   // padded mode stride
#define MT     128    // mode tile in MLP kernel
#define LAMBDA 0.01f

// Scratch spectra: (B, D, MP) real and imag
__device__ float g_Sr[(size_t)NBATCH * DCH * MP];
__device__ float g_Si[(size_t)NBATCH * DCH * MP];

extern __shared__ char smem_raw[];

// ---------------- packed f32x2 helpers (FFMA2 path) ----------------
typedef unsigned long long ull;

__device__ __forceinline__ ull bcast2(float v) {
    ull r; asm("mov.b64 %0, {%1, %1};" : "=l"(r) : "f"(v)); return r;
}
__device__ __forceinline__ ull pack2(float lo, float hi) {
    ull r; asm("mov.b64 %0, {%1, %2};" : "=l"(r) : "f"(lo), "f"(hi)); return r;
}
__device__ __forceinline__ void unpack2(ull a, float& lo, float& hi) {
    asm("mov.b64 {%0, %1}, %2;" : "=f"(lo), "=f"(hi) : "l"(a));
}
__device__ __forceinline__ void ffma2(ull& d, ull a, ull b) {
    asm("fma.rn.f32x2 %0, %1, %2, %0;" : "+l"(d) : "l"(a), "l"(b));
}

__device__ __forceinline__ float2 cmul(float2 a, float2 w) {
    return make_float2(a.x * w.x - a.y * w.y, a.x * w.y + a.y * w.x);
}
__device__ __forceinline__ float2 cadd(float2 a, float2 b) { return make_float2(a.x + b.x, a.y + b.y); }
__device__ __forceinline__ float2 csub(float2 a, float2 b) { return make_float2(a.x - b.x, a.y - b.y); }

// ---------------------------------------------------------------------------
// Forward FFT: radix-4 Stockham, 6 stages. One CTA per (batch, channel-pair).
// Real-pair trick: z = x[:,d0] + i x[:,d1].
// ---------------------------------------------------------------------------
__global__ __launch_bounds__(512) void fwd_fft_kernel(const float* __restrict__ x) {
    float2* bufA = reinterpret_cast<float2*>(smem_raw);
    float2* bufB = bufA + LSEQ;
    float2* tw   = bufB + LSEQ;          // 1024 roots e^{-2pi i j / 4096}
    const int tid = threadIdx.x;
    const int T   = 512;
    const int bi  = blockIdx.x;
    const int b   = bi / (DCH / 2);
    const int d0  = (bi % (DCH / 2)) * 2;

    for (int j = tid; j < LSEQ / 4; j += T) {
        float sv, cv;
        sincosf(-6.28318530717958647692f * (float)j / (float)LSEQ, &sv, &cv);
        tw[j] = make_float2(cv, sv);
    }
    const float* xb = x + (size_t)b * LSEQ * DCH + d0;
    for (int l = tid; l < LSEQ; l += T) {
        bufA[l] = *reinterpret_cast<const float2*>(xb + (size_t)l * DCH);
    }
    __syncthreads();

    float2* src = bufA;
    float2* dst = bufB;
    #pragma unroll
    for (int ls = 0; ls < 6; ls++) {
        const int s = 1 << (2 * ls);
        for (int t = tid; t < LSEQ / 4; t += T) {
            float2 a0 = src[t];
            float2 a1 = src[t + 1024];
            float2 a2 = src[t + 2048];
            float2 a3 = src[t + 3072];
            int q = t & (s - 1);
            float2 w1 = tw[t - q];            // e^{-2pi i p s / N}, p*s = t-q
            float2 w2 = cmul(w1, w1);
            float2 w3 = cmul(w2, w1);
            float2 t0 = cadd(a0, a2), t1 = csub(a0, a2);
            float2 t2 = cadd(a1, a3), t3 = csub(a1, a3);
            float2 u1 = make_float2(t1.x + t3.y, t1.y - t3.x);   // t1 - i*t3
            float2 u3 = make_float2(t1.x - t3.y, t1.y + t3.x);   // t1 + i*t3
            int base = 4 * t - 3 * q;
            dst[base]         = cadd(t0, t2);
            dst[base + s]     = cmul(u1, w1);
            dst[base + 2 * s] = cmul(csub(t0, t2), w2);
            dst[base + 3 * s] = cmul(u3, w3);
        }
        __syncthreads();
        float2* tmp = src; src = dst; dst = tmp;
    }
    // result in src (bufA), natural order. Separate Hermitian pair, ortho norm.
    const float scale = 0.5f / 64.0f;
    float* SrB = g_Sr + ((size_t)b * DCH + d0) * MP;
    float* SiB = g_Si + ((size_t)b * DCH + d0) * MP;
    for (int k = tid; k < NMODES; k += T) {
        float2 z1 = src[k];
        float2 z2 = src[(LSEQ - k) & (LSEQ - 1)];
        SrB[k]      = (z1.x + z2.x) * scale;   // Re A
        SiB[k]      = (z1.y - z2.y) * scale;   // Im A
        SrB[MP + k] = (z1.y + z2.y) * scale;   // Re B
        SiB[MP + k] = (z2.x - z1.x) * scale;   // Im B
    }
}

// ---------------------------------------------------------------------------
// Inverse FFT: radix-4 Stockham with conjugate twiddles.
// ---------------------------------------------------------------------------
__global__ __launch_bounds__(512) void inv_fft_kernel(const float* __restrict__ x,
                                                      float* __restrict__ y) {
    float2* bufA = reinterpret_cast<float2*>(smem_raw);
    float2* bufB = bufA + LSEQ;
    float2* tw   = bufB + LSEQ;
    const int tid = threadIdx.x;
    const int T   = 512;
    const int bi  = blockIdx.x;
    const int b   = bi / (DCH / 2);
    const int d0  = (bi % (DCH / 2)) * 2;

    for (int j = tid; j < LSEQ / 4; j += T) {
        float sv, cv;
        sincosf(6.28318530717958647692f * (float)j / (float)LSEQ, &sv, &cv);
        tw[j] = make_float2(cv, sv);
    }
    const float* SrB = g_Sr + ((size_t)b * DCH + d0) * MP;
    const float* SiB = g_Si + ((size_t)b * DCH + d0) * MP;
    for (int k = tid; k < NMODES; k += T) {
        float ar  = SrB[k],      ai  = SiB[k];
        float br  = SrB[MP + k], bi_ = SiB[MP + k];
        if (k == 0 || k == LSEQ / 2) { ai = 0.0f; bi_ = 0.0f; }
        bufA[k] = make_float2(ar - bi_, ai + br);
        if (k > 0 && k < LSEQ / 2)
            bufA[LSEQ - k] = make_float2(ar + bi_, br - ai);  // conj extension
    }
    __syncthreads();

    float2* src = bufA;
    float2* dst = bufB;
    #pragma unroll
    for (int ls = 0; ls < 6; ls++) {
        const int s = 1 << (2 * ls);
        for (int t = tid; t < LSEQ / 4; t += T) {
            float2 a0 = src[t];
            float2 a1 = src[t + 1024];
            float2 a2 = src[t + 2048];
            float2 a3 = src[t + 3072];
            int q = t & (s - 1);
            float2 w1 = tw[t - q];
            float2 w2 = cmul(w1, w1);
            float2 w3 = cmul(w2, w1);
            float2 t0 = cadd(a0, a2), t1 = csub(a0, a2);
            float2 t2 = cadd(a1, a3), t3 = csub(a1, a3);
            float2 u1 = make_float2(t1.x - t3.y, t1.y + t3.x);   // t1 + i*t3 (inverse)
            float2 u3 = make_float2(t1.x + t3.y, t1.y - t3.x);   // t1 - i*t3
            int base = 4 * t - 3 * q;
            dst[base]         = cadd(t0, t2);
            dst[base + s]     = cmul(u1, w1);
            dst[base + 2 * s] = cmul(csub(t0, t2), w2);
            dst[base + 3 * s] = cmul(u3, w3);
        }
        __syncthreads();
        float2* tmp = src; src = dst; dst = tmp;
    }
    const float scale = 1.0f / 64.0f;
    const float* xb = x + (size_t)b * LSEQ * DCH + d0;
    float*       yb = y + (size_t)b * LSEQ * DCH + d0;
    for (int l = tid; l < LSEQ; l += T) {
        float2 v  = src[l];
        float2 xv = *reinterpret_cast<const float2*>(xb + (size_t)l * DCH);
        float2 out = make_float2(xv.x + v.x * scale, xv.y + v.y * scale);
        *reinterpret_cast<float2*>(yb + (size_t)l * DCH) = out;
    }
}

// ---------------------------------------------------------------------------
// Per-mode complex block-diagonal MLP, packed f32x2 FMA.
// Grid: (17 mode-tiles, 8 blocks, 8 batch). 512 threads.
// Thread (lane = tid&31, ot = tid>>5): 4 consecutive modes lane*4..+3,
// 6 outputs ot*6..+5. Smem: W (72KB) + X/O1 shared buffer (96KB).
// ---------------------------------------------------------------------------
__global__ __launch_bounds__(512) void mlp_kernel(const float* __restrict__ w1,
                                                  const float* __restrict__ b1,
                                                  const float* __restrict__ w2,
                                                  const float* __restrict__ b2) {
    float* Wr = reinterpret_cast<float*>(smem_raw);    // [96][96]
    float* Wi = Wr + BS * BS;
    float* Xr = Wi + BS * BS;                          // [96][128], reused for O1
    float* Xi = Xr + BS * MT;

    const int tid  = threadIdx.x;
    const int n    = blockIdx.y;
    const int b    = blockIdx.z;
    const int m0   = blockIdx.x * MT;
    const int lane = tid & 31;
    const int ot   = tid >> 5;
    const bool full = (m0 + MT <= NMODES);

    // stage W1 (layout w1[c][n][i][o])
    {
        const float4* w1r4 = reinterpret_cast<const float4*>(w1 + (size_t)n * BS * BS);
        const float4* w1i4 = reinterpret_cast<const float4*>(w1 + (size_t)(NBLK + n) * BS * BS);
        for (int t = tid; t < BS * BS / 4; t += 512) {
            reinterpret_cast<float4*>(Wr)[t] = w1r4[t];
            reinterpret_cast<float4*>(Wi)[t] = w1i4[t];
        }
    }
    float* SrB = g_Sr + ((size_t)b * DCH + n * BS) * MP;
    float* SiB = g_Si + ((size_t)b * DCH + n * BS) * MP;
    for (int t = tid; t < BS * 32; t += 512) {
        int i = t >> 5, c = t & 31;
        int m = m0 + c * 4;
        float4 vr, vi;
        if (full) {
            vr = *reinterpret_cast<const float4*>(SrB + (size_t)i * MP + m);
            vi = *reinterpret_cast<const float4*>(SiB + (size_t)i * MP + m);
        } else {
            vr = make_float4(0.f, 0.f, 0.f, 0.f);
            vi = make_float4(0.f, 0.f, 0.f, 0.f);
            #pragma unroll
            for (int j = 0; j < 4; j++) {
                if (m + j < NMODES) {
                    (&vr.x)[j] = SrB[(size_t)i * MP + m + j];
                    (&vi.x)[j] = SiB[(size_t)i * MP + m + j];
                }
            }
        }
        *reinterpret_cast<float4*>(Xr + i * MT + c * 4) = vr;
        *reinterpret_cast<float4*>(Xi + i * MT + c * 4) = vi;
    }
    __syncthreads();

    const ull SGN2 = 0x8000000080000000ULL;

    // ---------------- layer 1 ----------------
    ull accR[12], accI[12];   // [oo][k], k = mode pair 0/1
    {
        const float* b1r = b1 + (size_t)n * BS + ot * 6;
        const float* b1i = b1 + (size_t)(NBLK + n) * BS + ot * 6;
        #pragma unroll
        for (int oo = 0; oo < 6; oo++) {
            ull vr = bcast2(b1r[oo]), vi = bcast2(b1i[oo]);
            accR[oo * 2] = vr; accR[oo * 2 + 1] = vr;
            accI[oo * 2] = vi; accI[oo * 2 + 1] = vi;
        }
    }
    {
        const float* xrp = Xr + lane * 4;
        const float* xip = Xi + lane * 4;
        const float* wrp = Wr + ot * 6;
        const float* wip = Wi + ot * 6;
        for (int i = 0; i < BS; i++) {
            float4 xr4 = *reinterpret_cast<const float4*>(xrp + i * MT);
            float4 xi4 = *reinterpret_cast<const float4*>(xip + i * MT);
            ull xr2a = pack2(xr4.x, xr4.y), xr2b = pack2(xr4.z, xr4.w);
            ull xi2a = pack2(xi4.x, xi4.y), xi2b = pack2(xi4.z, xi4.w);
            ull nxia = xi2a ^ SGN2, nxib = xi2b ^ SGN2;
            float2 wr01 = *reinterpret_cast<const float2*>(wrp + i * BS);
            float2 wr23 = *reinterpret_cast<const float2*>(wrp + i * BS + 2);
            float2 wr45 = *reinterpret_cast<const float2*>(wrp + i * BS + 4);
            float2 wi01 = *reinterpret_cast<const float2*>(wip + i * BS);
            float2 wi23 = *reinterpret_cast<const float2*>(wip + i * BS + 2);
            float2 wi45 = *reinterpret_cast<const float2*>(wip + i * BS + 4);
            float wrv[6] = {wr01.x, wr01.y, wr23.x, wr23.y, wr45.x, wr45.y};
            float wiv[6] = {wi01.x, wi01.y, wi23.x, wi23.y, wi45.x, wi45.y};
            #pragma unroll
            for (int oo = 0; oo < 6; oo++) {
                ull w_r = bcast2(wrv[oo]);
                ull w_i = bcast2(wiv[oo]);
                ffma2(accR[oo * 2],     w_r, xr2a); ffma2(accR[oo * 2],     w_i, nxia);
                ffma2(accR[oo * 2 + 1], w_r, xr2b); ffma2(accR[oo * 2 + 1], w_i, nxib);
                ffma2(accI[oo * 2],     w_r, xi2a); ffma2(accI[oo * 2],     w_i, xr2a);
                ffma2(accI[oo * 2 + 1], w_r, xi2b); ffma2(accI[oo * 2 + 1], w_i, xr2b);
            }
        }
    }
    __syncthreads();   // all X / W1 reads done

    // relu -> O1 (into X buffer); stage W2
    #pragma unroll
    for (int oo = 0; oo < 6; oo++) {
        int row = ot * 6 + oo;
        float r0, r1, r2, r3, i0, i1, i2, i3;
        unpack2(accR[oo * 2], r0, r1);  unpack2(accR[oo * 2 + 1], r2, r3);
        unpack2(accI[oo * 2], i0, i1);  unpack2(accI[oo * 2 + 1], i2, i3);
        *reinterpret_cast<float4*>(Xr + row * MT + lane * 4) =
            make_float4(fmaxf(r0, 0.f), fmaxf(r1, 0.f), fmaxf(r2, 0.f), fmaxf(r3, 0.f));
        *reinterpret_cast<float4*>(Xi + row * MT + lane * 4) =
            make_float4(fmaxf(i0, 0.f), fmaxf(i1, 0.f), fmaxf(i2, 0.f), fmaxf(i3, 0.f));
    }
    {
        const float4* w2r4 = reinterpret_cast<const float4*>(w2 + (size_t)n * BS * BS);
        const float4* w2i4 = reinterpret_cast<const float4*>(w2 + (size_t)(NBLK + n) * BS * BS);
        for (int t = tid; t < BS * BS / 4; t += 512) {
            reinterpret_cast<float4*>(Wr)[t] = w2r4[t];
            reinterpret_cast<float4*>(Wi)[t] = w2i4[t];
        }
    }
    __syncthreads();

    // ---------------- layer 2 ----------------
    {
        const float* b2r = b2 + (size_t)n * BS + ot * 6;
        const float* b2i = b2 + (size_t)(NBLK + n) * BS + ot * 6;
        #pragma unroll
        for (int oo = 0; oo < 6; oo++) {
            ull vr = bcast2(b2r[oo]), vi = bcast2(b2i[oo]);
            accR[oo * 2] = vr; accR[oo * 2 + 1] = vr;
            accI[oo * 2] = vi; accI[oo * 2 + 1] = vi;
        }
    }
    {
        const float* xrp = Xr + lane * 4;
        const float* xip = Xi + lane * 4;
        const float* wrp = Wr + ot * 6;
        const float* wip = Wi + ot * 6;
        for (int o = 0; o < BS; o++) {
            float4 xr4 = *reinterpret_cast<const float4*>(xrp + o * MT);
            float4 xi4 = *reinterpret_cast<const float4*>(xip + o * MT);
            ull xr2a = pack2(xr4.x, xr4.y), xr2b = pack2(xr4.z, xr4.w);
            ull xi2a = pack2(xi4.x, xi4.y), xi2b = pack2(xi4.z, xi4.w);
            ull nxia = xi2a ^ SGN2, nxib = xi2b ^ SGN2;
            float2 wr01 = *reinterpret_cast<const float2*>(wrp + o * BS);
            float2 wr23 = *reinterpret_cast<const float2*>(wrp + o * BS + 2);
            float2 wr45 = *reinterpret_cast<const float2*>(wrp + o * BS + 4);
            float2 wi01 = *reinterpret_cast<const float2*>(wip + o * BS);
            float2 wi23 = *reinterpret_cast<const float2*>(wip + o * BS + 2);
            float2 wi45 = *reinterpret_cast<const float2*>(wip + o * BS + 4);
            float wrv[6] = {wr01.x, wr01.y, wr23.x, wr23.y, wr45.x, wr45.y};
            float wiv[6] = {wi01.x, wi01.y, wi23.x, wi23.y, wi45.x, wi45.y};
            #pragma unroll
            for (int oo = 0; oo < 6; oo++) {
                ull w_r = bcast2(wrv[oo]);
                ull w_i = bcast2(wiv[oo]);
                ffma2(accR[oo * 2],     w_r, xr2a); ffma2(accR[oo * 2],     w_i, nxia);
                ffma2(accR[oo * 2 + 1], w_r, xr2b); ffma2(accR[oo * 2 + 1], w_i, nxib);
                ffma2(accI[oo * 2],     w_r, xi2a); ffma2(accI[oo * 2],     w_i, xr2a);
                ffma2(accI[oo * 2 + 1], w_r, xi2b); ffma2(accI[oo * 2 + 1], w_i, xr2b);
            }
        }
    }

    // softshrink + store
    #pragma unroll
    for (int oo = 0; oo < 6; oo++) {
        int row = ot * 6 + oo;
        float v[8];
        unpack2(accR[oo * 2], v[0], v[1]);  unpack2(accR[oo * 2 + 1], v[2], v[3]);
        unpack2(accI[oo * 2], v[4], v[5]);  unpack2(accI[oo * 2 + 1], v[6], v[7]);
        #pragma unroll
        for (int j = 0; j < 8; j++) {
            float t = fabsf(v[j]) - LAMBDA;
            v[j] = t > 0.f ? copysignf(t, v[j]) : 0.f;
        }
        int m = m0 + lane * 4;
        if (full) {
            *reinterpret_cast<float4*>(SrB + (size_t)row * MP + m) = make_float4(v[0], v[1], v[2], v[3]);
            *reinterpret_cast<float4*>(SiB + (size_t)row * MP + m) = make_float4(v[4], v[5], v[6], v[7]);
        } else {
            #pragma unroll
            for (int j = 0; j < 4; j++) {
                if (m + j < NMODES) {
                    SrB[(size_t)row * MP + m + j] = v[j];
                    SiB[(size_t)row * MP + m + j] = v[4 + j];
                }
            }
        }
    }
}

// ---------------------------------------------------------------------------
extern "C" void kernel_launch(void* const* d_in, const int* in_sizes, int n_in,
                              void* d_out, int out_size) {
    const float* x  = (const float*)d_in[0];
    const float* w1 = (const float*)d_in[1];
    const float* b1 = (const float*)d_in[2];
    const float* w2 = (const float*)d_in[3];
    const float* b2 = (const float*)d_in[4];
    float* y = (float*)d_out;

    const size_t fft_smem = (size_t)(2 * LSEQ + LSEQ / 4) * sizeof(float2);      // 73728
    const size_t mlp_smem = (size_t)(2 * BS * BS + 2 * BS * MT) * sizeof(float); // 172032

    cudaFuncSetAttribute(fwd_fft_kernel, cudaFuncAttributeMaxDynamicSharedMemorySize, (int)fft_smem);
    cudaFuncSetAttribute(inv_fft_kernel, cudaFuncAttributeMaxDynamicSharedMemorySize, (int)fft_smem);
    cudaFuncSetAttribute(mlp_kernel,     cudaFuncAttributeMaxDynamicSharedMemorySize, (int)mlp_smem);

    fwd_fft_kernel<<<NBATCH * DCH / 2, 512, fft_smem>>>(x);

    dim3 g((NMODES + MT - 1) / MT, NBLK, NBATCH);
    mlp_kernel<<<g, 512, mlp_smem>>>(w1, b1, w2, b2);

    inv_fft_kernel<<<NBATCH * DCH / 2, 512, fft_smem>>>(x, y);
}

// round 8
// speedup vs baseline: 1.3815x; 1.3815x over previous
#include <cuda_runtime.h>
#include <math.h>

#define LSEQ   4096
#define DCH    768
#define NBATCH 8
#define NBLK   8
#define BS     96
#define NMODES 2049   // LSEQ/2 + 1
#define MP     2064   // padded mode stride
#define MT     64     // mode tile in MLP kernel
#define LAMBDA 0.01f

// Scratch spectra: (B, D, MP) real and imag
__device__ float g_Sr[(size_t)NBATCH * DCH * MP];
__device__ float g_Si[(size_t)NBATCH * DCH * MP];

extern __shared__ char smem_raw[];

// ---------------- packed f32x2 helpers (FFMA2 path) ----------------
typedef unsigned long long ull;

__device__ __forceinline__ ull bcast2(float v) {
    ull r; asm("mov.b64 %0, {%1, %1};" : "=l"(r) : "f"(v)); return r;
}
__device__ __forceinline__ ull pack2(float lo, float hi) {
    ull r; asm("mov.b64 %0, {%1, %2};" : "=l"(r) : "f"(lo), "f"(hi)); return r;
}
__device__ __forceinline__ void unpack2(ull a, float& lo, float& hi) {
    asm("mov.b64 {%0, %1}, %2;" : "=f"(lo), "=f"(hi) : "l"(a));
}
__device__ __forceinline__ void ffma2(ull& d, ull a, ull b) {
    asm("fma.rn.f32x2 %0, %1, %2, %0;" : "+l"(d) : "l"(a), "l"(b));
}

// ---------------------------------------------------------------------------
// Forward FFT (R1-proven): radix-2 Stockham, 12 stages, 256 threads.
// One CTA per (batch, channel-pair). z = x[:,d0] + i x[:,d1].
// ---------------------------------------------------------------------------
__global__ __launch_bounds__(256) void fwd_fft_kernel(const float* __restrict__ x) {
    float2* bufA = reinterpret_cast<float2*>(smem_raw);
    float2* bufB = bufA + LSEQ;
    float2* tw   = bufB + LSEQ;          // 2048 roots e^{-2pi i j / 4096}
    const int tid = threadIdx.x;
    const int T   = 256;
    const int bi  = blockIdx.x;
    const int b   = bi / (DCH / 2);
    const int d0  = (bi % (DCH / 2)) * 2;

    for (int j = tid; j < LSEQ / 2; j += T) {
        float sv, cv;
        sincosf(-6.28318530717958647692f * (float)j / (float)LSEQ, &sv, &cv);
        tw[j] = make_float2(cv, sv);
    }
    const float* xb = x + (size_t)b * LSEQ * DCH + d0;
    for (int l = tid; l < LSEQ; l += T) {
        bufA[l] = *reinterpret_cast<const float2*>(xb + (size_t)l * DCH);
    }
    __syncthreads();

    float2* src = bufA;
    float2* dst = bufB;
    for (int ls = 0; ls < 12; ls++) {
        const int s = 1 << ls;
        for (int t = tid; t < LSEQ / 2; t += T) {
            float2 a = src[t];
            float2 c = src[t + LSEQ / 2];
            float2 w = tw[t & ~(s - 1)];
            float dx = a.x - c.x, dy = a.y - c.y;
            int o = t + (t & ~(s - 1));
            dst[o]     = make_float2(a.x + c.x, a.y + c.y);
            dst[o + s] = make_float2(dx * w.x - dy * w.y, dx * w.y + dy * w.x);
        }
        __syncthreads();
        float2* tmp = src; src = dst; dst = tmp;
    }
    const float scale = 0.5f / 64.0f;
    float* SrB = g_Sr + ((size_t)b * DCH + d0) * MP;
    float* SiB = g_Si + ((size_t)b * DCH + d0) * MP;
    for (int k = tid; k < NMODES; k += T) {
        float2 z1 = src[k];
        float2 z2 = src[(LSEQ - k) & (LSEQ - 1)];
        SrB[k]      = (z1.x + z2.x) * scale;
        SiB[k]      = (z1.y - z2.y) * scale;
        SrB[MP + k] = (z1.y + z2.y) * scale;
        SiB[MP + k] = (z2.x - z1.x) * scale;
    }
}

// ---------------------------------------------------------------------------
// Inverse FFT (R1-proven): radix-2 Stockham with conjugate twiddles.
// ---------------------------------------------------------------------------
__global__ __launch_bounds__(256) void inv_fft_kernel(const float* __restrict__ x,
                                                      float* __restrict__ y) {
    float2* bufA = reinterpret_cast<float2*>(smem_raw);
    float2* bufB = bufA + LSEQ;
    float2* tw   = bufB + LSEQ;
    const int tid = threadIdx.x;
    const int T   = 256;
    const int bi  = blockIdx.x;
    const int b   = bi / (DCH / 2);
    const int d0  = (bi % (DCH / 2)) * 2;

    for (int j = tid; j < LSEQ / 2; j += T) {
        float sv, cv;
        sincosf(6.28318530717958647692f * (float)j / (float)LSEQ, &sv, &cv);
        tw[j] = make_float2(cv, sv);
    }
    const float* SrB = g_Sr + ((size_t)b * DCH + d0) * MP;
    const float* SiB = g_Si + ((size_t)b * DCH + d0) * MP;
    for (int k = tid; k < NMODES; k += T) {
        float ar  = SrB[k],      ai  = SiB[k];
        float br  = SrB[MP + k], bi_ = SiB[MP + k];
        if (k == 0 || k == LSEQ / 2) { ai = 0.0f; bi_ = 0.0f; }
        bufA[k] = make_float2(ar - bi_, ai + br);
        if (k > 0 && k < LSEQ / 2)
            bufA[LSEQ - k] = make_float2(ar + bi_, br - ai);
    }
    __syncthreads();

    float2* src = bufA;
    float2* dst = bufB;
    for (int ls = 0; ls < 12; ls++) {
        const int s = 1 << ls;
        for (int t = tid; t < LSEQ / 2; t += T) {
            float2 a = src[t];
            float2 c = src[t + LSEQ / 2];
            float2 w = tw[t & ~(s - 1)];
            float dx = a.x - c.x, dy = a.y - c.y;
            int o = t + (t & ~(s - 1));
            dst[o]     = make_float2(a.x + c.x, a.y + c.y);
            dst[o + s] = make_float2(dx * w.x - dy * w.y, dx * w.y + dy * w.x);
        }
        __syncthreads();
        float2* tmp = src; src = dst; dst = tmp;
    }
    const float scale = 1.0f / 64.0f;
    const float* xb = x + (size_t)b * LSEQ * DCH + d0;
    float*       yb = y + (size_t)b * LSEQ * DCH + d0;
    for (int l = tid; l < LSEQ; l += T) {
        float2 v  = src[l];
        float2 xv = *reinterpret_cast<const float2*>(xb + (size_t)l * DCH);
        float2 out = make_float2(xv.x + v.x * scale, xv.y + v.y * scale);
        *reinterpret_cast<float2*>(yb + (size_t)l * DCH) = out;
    }
}

// ---------------------------------------------------------------------------
// Per-mode complex block-diagonal MLP, packed f32x2 FMA, 256 threads.
// Grid: (33 mode-tiles, 8 blocks, 8 batch).
// Thread (lane = tid&15, ot = tid>>4): 4 consecutive modes lane*4..+3,
// 6 outputs ot*6..+5. Smem: W (72KB) + X/O1 shared buffer (48KB) = 120KB.
// 48 FFMA2 (= 96 lane-FMAs) per K-step per thread.
// ---------------------------------------------------------------------------
__global__ __launch_bounds__(256) void mlp_kernel(const float* __restrict__ w1,
                                                  const float* __restrict__ b1,
                                                  const float* __restrict__ w2,
                                                  const float* __restrict__ b2) {
    float* Wr = reinterpret_cast<float*>(smem_raw);    // [96][96]
    float* Wi = Wr + BS * BS;
    float* Xr = Wi + BS * BS;                          // [96][64], reused for O1
    float* Xi = Xr + BS * MT;

    const int tid  = threadIdx.x;
    const int n    = blockIdx.y;
    const int b    = blockIdx.z;
    const int m0   = blockIdx.x * MT;
    const int lane = tid & 15;
    const int ot   = tid >> 4;
    const bool full = (m0 + MT <= NMODES);

    // stage W1 (layout w1[c][n][i][o])
    {
        const float4* w1r4 = reinterpret_cast<const float4*>(w1 + (size_t)n * BS * BS);
        const float4* w1i4 = reinterpret_cast<const float4*>(w1 + (size_t)(NBLK + n) * BS * BS);
        for (int t = tid; t < BS * BS / 4; t += 256) {
            reinterpret_cast<float4*>(Wr)[t] = w1r4[t];
            reinterpret_cast<float4*>(Wi)[t] = w1i4[t];
        }
    }
    float* SrB = g_Sr + ((size_t)b * DCH + n * BS) * MP;
    float* SiB = g_Si + ((size_t)b * DCH + n * BS) * MP;
    for (int t = tid; t < BS * 16; t += 256) {
        int i = t >> 4, c = t & 15;
        int m = m0 + c * 4;
        float4 vr, vi;
        if (full) {
            vr = *reinterpret_cast<const float4*>(SrB + (size_t)i * MP + m);
            vi = *reinterpret_cast<const float4*>(SiB + (size_t)i * MP + m);
        } else {
            vr = make_float4(0.f, 0.f, 0.f, 0.f);
            vi = make_float4(0.f, 0.f, 0.f, 0.f);
            #pragma unroll
            for (int j = 0; j < 4; j++) {
                if (m + j < NMODES) {
                    (&vr.x)[j] = SrB[(size_t)i * MP + m + j];
                    (&vi.x)[j] = SiB[(size_t)i * MP + m + j];
                }
            }
        }
        *reinterpret_cast<float4*>(Xr + i * MT + c * 4) = vr;
        *reinterpret_cast<float4*>(Xi + i * MT + c * 4) = vi;
    }
    __syncthreads();

    const ull SGN2 = 0x8000000080000000ULL;

    // ---------------- layer 1 ----------------
    ull accR[12], accI[12];   // [oo][mode-pair]
    {
        const float* b1r = b1 + (size_t)n * BS + ot * 6;
        const float* b1i = b1 + (size_t)(NBLK + n) * BS + ot * 6;
        #pragma unroll
        for (int oo = 0; oo < 6; oo++) {
            ull vr = bcast2(b1r[oo]), vi = bcast2(b1i[oo]);
            accR[oo * 2] = vr; accR[oo * 2 + 1] = vr;
            accI[oo * 2] = vi; accI[oo * 2 + 1] = vi;
        }
    }
    {
        const float* xrp = Xr + lane * 4;
        const float* xip = Xi + lane * 4;
        const float* wrp = Wr + ot * 6;
        const float* wip = Wi + ot * 6;
        for (int i = 0; i < BS; i++) {
            float4 xr4 = *reinterpret_cast<const float4*>(xrp + i * MT);
            float4 xi4 = *reinterpret_cast<const float4*>(xip + i * MT);
            ull xr2a = pack2(xr4.x, xr4.y), xr2b = pack2(xr4.z, xr4.w);
            ull xi2a = pack2(xi4.x, xi4.y), xi2b = pack2(xi4.z, xi4.w);
            ull nxia = xi2a ^ SGN2, nxib = xi2b ^ SGN2;
            float2 wr01 = *reinterpret_cast<const float2*>(wrp + i * BS);
            float2 wr23 = *reinterpret_cast<const float2*>(wrp + i * BS + 2);
            float2 wr45 = *reinterpret_cast<const float2*>(wrp + i * BS + 4);
            float2 wi01 = *reinterpret_cast<const float2*>(wip + i * BS);
            float2 wi23 = *reinterpret_cast<const float2*>(wip + i * BS + 2);
            float2 wi45 = *reinterpret_cast<const float2*>(wip + i * BS + 4);
            float wrv[6] = {wr01.x, wr01.y, wr23.x, wr23.y, wr45.x, wr45.y};
            float wiv[6] = {wi01.x, wi01.y, wi23.x, wi23.y, wi45.x, wi45.y};
            #pragma unroll
            for (int oo = 0; oo < 6; oo++) {
                ull w_r = bcast2(wrv[oo]);
                ull w_i = bcast2(wiv[oo]);
                ffma2(accR[oo * 2],     w_r, xr2a); ffma2(accR[oo * 2],     w_i, nxia);
                ffma2(accR[oo * 2 + 1], w_r, xr2b); ffma2(accR[oo * 2 + 1], w_i, nxib);
                ffma2(accI[oo * 2],     w_r, xi2a); ffma2(accI[oo * 2],     w_i, xr2a);
                ffma2(accI[oo * 2 + 1], w_r, xi2b); ffma2(accI[oo * 2 + 1], w_i, xr2b);
            }
        }
    }
    __syncthreads();   // all X / W1 reads done

    // relu -> O1 (into X buffer); stage W2
    #pragma unroll
    for (int oo = 0; oo < 6; oo++) {
        int row = ot * 6 + oo;
        float r0, r1, r2, r3, i0, i1, i2, i3;
        unpack2(accR[oo * 2], r0, r1);  unpack2(accR[oo * 2 + 1], r2, r3);
        unpack2(accI[oo * 2], i0, i1);  unpack2(accI[oo * 2 + 1], i2, i3);
        *reinterpret_cast<float4*>(Xr + row * MT + lane * 4) =
            make_float4(fmaxf(r0, 0.f), fmaxf(r1, 0.f), fmaxf(r2, 0.f), fmaxf(r3, 0.f));
        *reinterpret_cast<float4*>(Xi + row * MT + lane * 4) =
            make_float4(fmaxf(i0, 0.f), fmaxf(i1, 0.f), fmaxf(i2, 0.f), fmaxf(i3, 0.f));
    }
    {
        const float4* w2r4 = reinterpret_cast<const float4*>(w2 + (size_t)n * BS * BS);
        const float4* w2i4 = reinterpret_cast<const float4*>(w2 + (size_t)(NBLK + n) * BS * BS);
        for (int t = tid; t < BS * BS / 4; t += 256) {
            reinterpret_cast<float4*>(Wr)[t] = w2r4[t];
            reinterpret_cast<float4*>(Wi)[t] = w2i4[t];
        }
    }
    __syncthreads();

    // ---------------- layer 2 ----------------
    {
        const float* b2r = b2 + (size_t)n * BS + ot * 6;
        const float* b2i = b2 + (size_t)(NBLK + n) * BS + ot * 6;
        #pragma unroll
        for (int oo = 0; oo < 6; oo++) {
            ull vr = bcast2(b2r[oo]), vi = bcast2(b2i[oo]);
            accR[oo * 2] = vr; accR[oo * 2 + 1] = vr;
            accI[oo * 2] = vi; accI[oo * 2 + 1] = vi;
        }
    }
    {
        const float* xrp = Xr + lane * 4;
        const float* xip = Xi + lane * 4;
        const float* wrp = Wr + ot * 6;
        const float* wip = Wi + ot * 6;
        for (int o = 0; o < BS; o++) {
            float4 xr4 = *reinterpret_cast<const float4*>(xrp + o * MT);
            float4 xi4 = *reinterpret_cast<const float4*>(xip + o * MT);
            ull xr2a = pack2(xr4.x, xr4.y), xr2b = pack2(xr4.z, xr4.w);
            ull xi2a = pack2(xi4.x, xi4.y), xi2b = pack2(xi4.z, xi4.w);
            ull nxia = xi2a ^ SGN2, nxib = xi2b ^ SGN2;
            float2 wr01 = *reinterpret_cast<const float2*>(wrp + o * BS);
            float2 wr23 = *reinterpret_cast<const float2*>(wrp + o * BS + 2);
            float2 wr45 = *reinterpret_cast<const float2*>(wrp + o * BS + 4);
            float2 wi01 = *reinterpret_cast<const float2*>(wip + o * BS);
            float2 wi23 = *reinterpret_cast<const float2*>(wip + o * BS + 2);
            float2 wi45 = *reinterpret_cast<const float2*>(wip + o * BS + 4);
            float wrv[6] = {wr01.x, wr01.y, wr23.x, wr23.y, wr45.x, wr45.y};
            float wiv[6] = {wi01.x, wi01.y, wi23.x, wi23.y, wi45.x, wi45.y};
            #pragma unroll
            for (int oo = 0; oo < 6; oo++) {
                ull w_r = bcast2(wrv[oo]);
                ull w_i = bcast2(wiv[oo]);
                ffma2(accR[oo * 2],     w_r, xr2a); ffma2(accR[oo * 2],     w_i, nxia);
                ffma2(accR[oo * 2 + 1], w_r, xr2b); ffma2(accR[oo * 2 + 1], w_i, nxib);
                ffma2(accI[oo * 2],     w_r, xi2a); ffma2(accI[oo * 2],     w_i, xr2a);
                ffma2(accI[oo * 2 + 1], w_r, xi2b); ffma2(accI[oo * 2 + 1], w_i, xr2b);
            }
        }
    }

    // softshrink + store
    #pragma unroll
    for (int oo = 0; oo < 6; oo++) {
        int row = ot * 6 + oo;
        float v[8];
        unpack2(accR[oo * 2], v[0], v[1]);  unpack2(accR[oo * 2 + 1], v[2], v[3]);
        unpack2(accI[oo * 2], v[4], v[5]);  unpack2(accI[oo * 2 + 1], v[6], v[7]);
        #pragma unroll
        for (int j = 0; j < 8; j++) {
            float t = fabsf(v[j]) - LAMBDA;
            v[j] = t > 0.f ? copysignf(t, v[j]) : 0.f;
        }
        int m = m0 + lane * 4;
        if (full) {
            *reinterpret_cast<float4*>(SrB + (size_t)row * MP + m) = make_float4(v[0], v[1], v[2], v[3]);
            *reinterpret_cast<float4*>(SiB + (size_t)row * MP + m) = make_float4(v[4], v[5], v[6], v[7]);
        } else {
            #pragma unroll
            for (int j = 0; j < 4; j++) {
                if (m + j < NMODES) {
                    SrB[(size_t)row * MP + m + j] = v[j];
                    SiB[(size_t)row * MP + m + j] = v[4 + j];
                }
            }
        }
    }
}

// ---------------------------------------------------------------------------
extern "C" void kernel_launch(void* const* d_in, const int* in_sizes, int n_in,
                              void* d_out, int out_size) {
    const float* x  = (const float*)d_in[0];
    const float* w1 = (const float*)d_in[1];
    const float* b1 = (const float*)d_in[2];
    const float* w2 = (const float*)d_in[3];
    const float* b2 = (const float*)d_in[4];
    float* y = (float*)d_out;

    const size_t fft_smem = (size_t)(2 * LSEQ + LSEQ / 2) * sizeof(float2);      // 81920
    const size_t mlp_smem = (size_t)(2 * BS * BS + 2 * BS * MT) * sizeof(float); // 122880

    cudaFuncSetAttribute(fwd_fft_kernel, cudaFuncAttributeMaxDynamicSharedMemorySize, (int)fft_smem);
    cudaFuncSetAttribute(inv_fft_kernel, cudaFuncAttributeMaxDynamicSharedMemorySize, (int)fft_smem);
    cudaFuncSetAttribute(mlp_kernel,     cudaFuncAttributeMaxDynamicSharedMemorySize, (int)mlp_smem);

    fwd_fft_kernel<<<NBATCH * DCH / 2, 256, fft_smem>>>(x);

    dim3 g((NMODES + MT - 1) / MT, NBLK, NBATCH);
    mlp_kernel<<<g, 256, mlp_smem>>>(w1, b1, w2, b2);

    inv_fft_kernel<<<NBATCH * DCH / 2, 256, fft_smem>>>(x, y);
}

// round 9
// speedup vs baseline: 1.5963x; 1.1555x over previous
#include <cuda_runtime.h>
#include <math.h>

#define LSEQ   4096
#define DCH    768
#define NBATCH 8
#define NBLK   8
#define BS     96
#define NMODES 2049   // LSEQ/2 + 1
#define MP     2064   // padded mode stride
#define MT     128    // mode tile in MLP kernel
#define LAMBDA 0.01f
#define PAIRS_PER_CTA 4

// Scratch spectra: (B, D, MP) real and imag
__device__ float g_Sr[(size_t)NBATCH * DCH * MP];
__device__ float g_Si[(size_t)NBATCH * DCH * MP];

extern __shared__ char smem_raw[];

// ---------------- packed f32x2 helpers (FFMA2 path) ----------------
typedef unsigned long long ull;

__device__ __forceinline__ ull bcast2(float v) {
    ull r; asm("mov.b64 %0, {%1, %1};" : "=l"(r) : "f"(v)); return r;
}
__device__ __forceinline__ void unpack2(ull a, float& lo, float& hi) {
    asm("mov.b64 {%0, %1}, %2;" : "=f"(lo), "=f"(hi) : "l"(a));
}
__device__ __forceinline__ void ffma2(ull& d, ull a, ull b) {
    asm("fma.rn.f32x2 %0, %1, %2, %0;" : "+l"(d) : "l"(a), "l"(b));
}

// ---------------------------------------------------------------------------
// Forward FFT: 4 channel-pairs per CTA, 1024 threads (sub-group of 256 per
// pair). Radix-2 Stockham, 12 stages, SINGLE buffer per pair via
// read-regs / sync / write. Coalesced float4 gmem loads (8 channels/CTA).
// smem: 4 * 4096 float2 bufs + 2048 float2 twiddles = 147456 B.
// ---------------------------------------------------------------------------
__global__ __launch_bounds__(1024) void fwd_fft_kernel(const float* __restrict__ x) {
    float2* buf = reinterpret_cast<float2*>(smem_raw);       // [4][4096]
    float2* tw  = buf + PAIRS_PER_CTA * LSEQ;                // [2048]
    const int tid = threadIdx.x;
    const int sub = tid >> 8;          // 0..3  (pair within CTA)
    const int st  = tid & 255;         // thread within sub-group
    const int bi  = blockIdx.x;
    const int b   = bi / (DCH / 8);
    const int c0  = (bi % (DCH / 8)) * 8;

    for (int j = tid; j < LSEQ / 2; j += 1024) {
        float sv, cv;
        sincosf(-6.28318530717958647692f * (float)j / (float)LSEQ, &sv, &cv);
        tw[j] = make_float2(cv, sv);
    }
    // coalesced slab load: 8 channels = 2 float4 per row
    const float* xs = x + (size_t)b * LSEQ * DCH + c0;
    for (int i = tid; i < LSEQ * 2; i += 1024) {
        int l = i >> 1, h = i & 1;
        float4 v = *reinterpret_cast<const float4*>(xs + (size_t)l * DCH + h * 4);
        buf[(2 * h)     * LSEQ + l] = make_float2(v.x, v.y);
        buf[(2 * h + 1) * LSEQ + l] = make_float2(v.z, v.w);
    }
    __syncthreads();

    float2* bp = buf + sub * LSEQ;
    for (int ls = 0; ls < 12; ls++) {
        const int s = 1 << ls;
        float2 a[8], c[8];
        #pragma unroll
        for (int k = 0; k < 8; k++) {
            int bt = st + (k << 8);
            a[k] = bp[bt];
            c[k] = bp[bt + 2048];
        }
        __syncthreads();
        #pragma unroll
        for (int k = 0; k < 8; k++) {
            int bt = st + (k << 8);
            int r  = bt & ~(s - 1);
            float2 w = tw[r];
            float dx = a[k].x - c[k].x, dy = a[k].y - c[k].y;
            int o = bt + r;
            bp[o]     = make_float2(a[k].x + c[k].x, a[k].y + c[k].y);
            bp[o + s] = make_float2(dx * w.x - dy * w.y, dx * w.y + dy * w.x);
        }
        __syncthreads();
    }
    // Hermitian separation for this pair, ortho norm
    const int d0 = c0 + 2 * sub;
    const float scale = 0.5f / 64.0f;
    float* SrB = g_Sr + ((size_t)b * DCH + d0) * MP;
    float* SiB = g_Si + ((size_t)b * DCH + d0) * MP;
    for (int k = st; k < NMODES; k += 256) {
        float2 z1 = bp[k];
        float2 z2 = bp[(LSEQ - k) & (LSEQ - 1)];
        SrB[k]      = (z1.x + z2.x) * scale;
        SiB[k]      = (z1.y - z2.y) * scale;
        SrB[MP + k] = (z1.y + z2.y) * scale;
        SiB[MP + k] = (z2.x - z1.x) * scale;
    }
}

// ---------------------------------------------------------------------------
// Inverse FFT: same structure, conjugate twiddles, residual add, coalesced
// float4 output stores.
// ---------------------------------------------------------------------------
__global__ __launch_bounds__(1024) void inv_fft_kernel(const float* __restrict__ x,
                                                       float* __restrict__ y) {
    float2* buf = reinterpret_cast<float2*>(smem_raw);
    float2* tw  = buf + PAIRS_PER_CTA * LSEQ;
    const int tid = threadIdx.x;
    const int sub = tid >> 8;
    const int st  = tid & 255;
    const int bi  = blockIdx.x;
    const int b   = bi / (DCH / 8);
    const int c0  = (bi % (DCH / 8)) * 8;
    const int d0  = c0 + 2 * sub;

    for (int j = tid; j < LSEQ / 2; j += 1024) {
        float sv, cv;
        sincosf(6.28318530717958647692f * (float)j / (float)LSEQ, &sv, &cv);
        tw[j] = make_float2(cv, sv);
    }
    float2* bp = buf + sub * LSEQ;
    const float* SrB = g_Sr + ((size_t)b * DCH + d0) * MP;
    const float* SiB = g_Si + ((size_t)b * DCH + d0) * MP;
    for (int k = st; k < NMODES; k += 256) {
        float ar  = SrB[k],      ai  = SiB[k];
        float br  = SrB[MP + k], bi_ = SiB[MP + k];
        if (k == 0 || k == LSEQ / 2) { ai = 0.0f; bi_ = 0.0f; }
        bp[k] = make_float2(ar - bi_, ai + br);
        if (k > 0 && k < LSEQ / 2)
            bp[LSEQ - k] = make_float2(ar + bi_, br - ai);
    }
    __syncthreads();

    for (int ls = 0; ls < 12; ls++) {
        const int s = 1 << ls;
        float2 a[8], c[8];
        #pragma unroll
        for (int k = 0; k < 8; k++) {
            int bt = st + (k << 8);
            a[k] = bp[bt];
            c[k] = bp[bt + 2048];
        }
        __syncthreads();
        #pragma unroll
        for (int k = 0; k < 8; k++) {
            int bt = st + (k << 8);
            int r  = bt & ~(s - 1);
            float2 w = tw[r];
            float dx = a[k].x - c[k].x, dy = a[k].y - c[k].y;
            int o = bt + r;
            bp[o]     = make_float2(a[k].x + c[k].x, a[k].y + c[k].y);
            bp[o + s] = make_float2(dx * w.x - dy * w.y, dx * w.y + dy * w.x);
        }
        __syncthreads();
    }
    const float sc = 1.0f / 64.0f;
    const float* xs = x + (size_t)b * LSEQ * DCH + c0;
    float*       ys = y + (size_t)b * LSEQ * DCH + c0;
    for (int i = tid; i < LSEQ * 2; i += 1024) {
        int l = i >> 1, h = i & 1;
        float2 u  = buf[(2 * h)     * LSEQ + l];
        float2 v2 = buf[(2 * h + 1) * LSEQ + l];
        float4 xv = *reinterpret_cast<const float4*>(xs + (size_t)l * DCH + h * 4);
        float4 out = make_float4(xv.x + u.x * sc,  xv.y + u.y * sc,
                                 xv.z + v2.x * sc, xv.w + v2.y * sc);
        *reinterpret_cast<float4*>(ys + (size_t)l * DCH + h * 4) = out;
    }
}

// ---------------------------------------------------------------------------
// Per-mode complex block-diagonal MLP, packed f32x2 FMA, 256 threads.
// Grid: (17 mode-tiles, 8 blocks, 8 batch). 8 modes per thread.
// lane = tid&15 -> modes lane*8..+7; ot = tid>>4 -> outputs ot*6..+5.
// Per K-step: 96 FFMA2 + 4 LDS.128 + 6 LDS.64 + 12 bcasts.
// Smem: W (72KB) + X/O1 (96KB) = 168KB.
// ---------------------------------------------------------------------------
__global__ __launch_bounds__(256) void mlp_kernel(const float* __restrict__ w1,
                                                  const float* __restrict__ b1,
                                                  const float* __restrict__ w2,
                                                  const float* __restrict__ b2) {
    float* Wr = reinterpret_cast<float*>(smem_raw);    // [96][96]
    float* Wi = Wr + BS * BS;
    float* Xr = Wi + BS * BS;                          // [96][128], reused for O1
    float* Xi = Xr + BS * MT;

    const int tid  = threadIdx.x;
    const int n    = blockIdx.y;
    const int b    = blockIdx.z;
    const int m0   = blockIdx.x * MT;
    const int lane = tid & 15;
    const int ot   = tid >> 4;
    const bool full = (m0 + MT <= NMODES);

    // stage W1 (layout w1[c][n][i][o])
    {
        const float4* w1r4 = reinterpret_cast<const float4*>(w1 + (size_t)n * BS * BS);
        const float4* w1i4 = reinterpret_cast<const float4*>(w1 + (size_t)(NBLK + n) * BS * BS);
        for (int t = tid; t < BS * BS / 4; t += 256) {
            reinterpret_cast<float4*>(Wr)[t] = w1r4[t];
            reinterpret_cast<float4*>(Wi)[t] = w1i4[t];
        }
    }
    float* SrB = g_Sr + ((size_t)b * DCH + n * BS) * MP;
    float* SiB = g_Si + ((size_t)b * DCH + n * BS) * MP;
    for (int t = tid; t < BS * (MT / 4); t += 256) {
        int i = t >> 5, c = t & 31;
        int m = m0 + c * 4;
        float4 vr, vi;
        if (full) {
            vr = *reinterpret_cast<const float4*>(SrB + (size_t)i * MP + m);
            vi = *reinterpret_cast<const float4*>(SiB + (size_t)i * MP + m);
        } else {
            vr = make_float4(0.f, 0.f, 0.f, 0.f);
            vi = make_float4(0.f, 0.f, 0.f, 0.f);
            #pragma unroll
            for (int j = 0; j < 4; j++) {
                if (m + j < NMODES) {
                    (&vr.x)[j] = SrB[(size_t)i * MP + m + j];
                    (&vi.x)[j] = SiB[(size_t)i * MP + m + j];
                }
            }
        }
        *reinterpret_cast<float4*>(Xr + i * MT + c * 4) = vr;
        *reinterpret_cast<float4*>(Xi + i * MT + c * 4) = vi;
    }
    __syncthreads();

    const ull SGN2 = 0x8000000080000000ULL;

    // ---------------- layer 1 ----------------
    ull accR[6][4], accI[6][4];
    {
        const float* b1r = b1 + (size_t)n * BS + ot * 6;
        const float* b1i = b1 + (size_t)(NBLK + n) * BS + ot * 6;
        #pragma unroll
        for (int oo = 0; oo < 6; oo++) {
            ull vr = bcast2(b1r[oo]), vi = bcast2(b1i[oo]);
            #pragma unroll
            for (int j = 0; j < 4; j++) { accR[oo][j] = vr; accI[oo][j] = vi; }
        }
    }
    {
        const float* xrp = Xr + lane * 8;
        const float* xip = Xi + lane * 8;
        const float* wrp = Wr + ot * 6;
        const float* wip = Wi + ot * 6;
        for (int i = 0; i < BS; i++) {
            ulonglong2 xra = *reinterpret_cast<const ulonglong2*>(xrp + i * MT);
            ulonglong2 xrb = *reinterpret_cast<const ulonglong2*>(xrp + i * MT + 4);
            ulonglong2 xia = *reinterpret_cast<const ulonglong2*>(xip + i * MT);
            ulonglong2 xib = *reinterpret_cast<const ulonglong2*>(xip + i * MT + 4);
            ull xr_[4] = {xra.x, xra.y, xrb.x, xrb.y};
            ull xi_[4] = {xia.x, xia.y, xib.x, xib.y};
            ull nxi[4] = {xia.x ^ SGN2, xia.y ^ SGN2, xib.x ^ SGN2, xib.y ^ SGN2};
            float2 wr01 = *reinterpret_cast<const float2*>(wrp + i * BS);
            float2 wr23 = *reinterpret_cast<const float2*>(wrp + i * BS + 2);
            float2 wr45 = *reinterpret_cast<const float2*>(wrp + i * BS + 4);
            float2 wi01 = *reinterpret_cast<const float2*>(wip + i * BS);
            float2 wi23 = *reinterpret_cast<const float2*>(wip + i * BS + 2);
            float2 wi45 = *reinterpret_cast<const float2*>(wip + i * BS + 4);
            float wrv[6] = {wr01.x, wr01.y, wr23.x, wr23.y, wr45.x, wr45.y};
            float wiv[6] = {wi01.x, wi01.y, wi23.x, wi23.y, wi45.x, wi45.y};
            #pragma unroll
            for (int oo = 0; oo < 6; oo++) {
                ull w_r = bcast2(wrv[oo]);
                ull w_i = bcast2(wiv[oo]);
                #pragma unroll
                for (int j = 0; j < 4; j++) {
                    ffma2(accR[oo][j], w_r, xr_[j]); ffma2(accR[oo][j], w_i, nxi[j]);
                    ffma2(accI[oo][j], w_r, xi_[j]); ffma2(accI[oo][j], w_i, xr_[j]);
                }
            }
        }
    }
    __syncthreads();   // all X / W1 reads done

    // relu -> O1 (into X buffer); stage W2
    #pragma unroll
    for (int oo = 0; oo < 6; oo++) {
        int row = ot * 6 + oo;
        float r[8], im[8];
        #pragma unroll
        for (int j = 0; j < 4; j++) {
            unpack2(accR[oo][j], r[2 * j], r[2 * j + 1]);
            unpack2(accI[oo][j], im[2 * j], im[2 * j + 1]);
        }
        *reinterpret_cast<float4*>(Xr + row * MT + lane * 8) =
            make_float4(fmaxf(r[0], 0.f), fmaxf(r[1], 0.f), fmaxf(r[2], 0.f), fmaxf(r[3], 0.f));
        *reinterpret_cast<float4*>(Xr + row * MT + lane * 8 + 4) =
            make_float4(fmaxf(r[4], 0.f), fmaxf(r[5], 0.f), fmaxf(r[6], 0.f), fmaxf(r[7], 0.f));
        *reinterpret_cast<float4*>(Xi + row * MT + lane * 8) =
            make_float4(fmaxf(im[0], 0.f), fmaxf(im[1], 0.f), fmaxf(im[2], 0.f), fmaxf(im[3], 0.f));
        *reinterpret_cast<float4*>(Xi + row * MT + lane * 8 + 4) =
            make_float4(fmaxf(im[4], 0.f), fmaxf(im[5], 0.f), fmaxf(im[6], 0.f), fmaxf(im[7], 0.f));
    }
    {
        const float4* w2r4 = reinterpret_cast<const float4*>(w2 + (size_t)n * BS * BS);
        const float4* w2i4 = reinterpret_cast<const float4*>(w2 + (size_t)(NBLK + n) * BS * BS);
        for (int t = tid; t < BS * BS / 4; t += 256) {
            reinterpret_cast<float4*>(Wr)[t] = w2r4[t];
            reinterpret_cast<float4*>(Wi)[t] = w2i4[t];
        }
    }
    __syncthreads();

    // ---------------- layer 2 ----------------
    {
        const float* b2r = b2 + (size_t)n * BS + ot * 6;
        const float* b2i = b2 + (size_t)(NBLK + n) * BS + ot * 6;
        #pragma unroll
        for (int oo = 0; oo < 6; oo++) {
            ull vr = bcast2(b2r[oo]), vi = bcast2(b2i[oo]);
            #pragma unroll
            for (int j = 0; j < 4; j++) { accR[oo][j] = vr; accI[oo][j] = vi; }
        }
    }
    {
        const float* xrp = Xr + lane * 8;
        const float* xip = Xi + lane * 8;
        const float* wrp = Wr + ot * 6;
        const float* wip = Wi + ot * 6;
        for (int o = 0; o < BS; o++) {
            ulonglong2 xra = *reinterpret_cast<const ulonglong2*>(xrp + o * MT);
            ulonglong2 xrb = *reinterpret_cast<const ulonglong2*>(xrp + o * MT + 4);
            ulonglong2 xia = *reinterpret_cast<const ulonglong2*>(xip + o * MT);
            ulonglong2 xib = *reinterpret_cast<const ulonglong2*>(xip + o * MT + 4);
            ull xr_[4] = {xra.x, xra.y, xrb.x, xrb.y};
            ull xi_[4] = {xia.x, xia.y, xib.x, xib.y};
            ull nxi[4] = {xia.x ^ SGN2, xia.y ^ SGN2, xib.x ^ SGN2, xib.y ^ SGN2};
            float2 wr01 = *reinterpret_cast<const float2*>(wrp + o * BS);
            float2 wr23 = *reinterpret_cast<const float2*>(wrp + o * BS + 2);
            float2 wr45 = *reinterpret_cast<const float2*>(wrp + o * BS + 4);
            float2 wi01 = *reinterpret_cast<const float2*>(wip + o * BS);
            float2 wi23 = *reinterpret_cast<const float2*>(wip + o * BS + 2);
            float2 wi45 = *reinterpret_cast<const float2*>(wip + o * BS + 4);
            float wrv[6] = {wr01.x, wr01.y, wr23.x, wr23.y, wr45.x, wr45.y};
            float wiv[6] = {wi01.x, wi01.y, wi23.x, wi23.y, wi45.x, wi45.y};
            #pragma unroll
            for (int oo = 0; oo < 6; oo++) {
                ull w_r = bcast2(wrv[oo]);
                ull w_i = bcast2(wiv[oo]);
                #pragma unroll
                for (int j = 0; j < 4; j++) {
                    ffma2(accR[oo][j], w_r, xr_[j]); ffma2(accR[oo][j], w_i, nxi[j]);
                    ffma2(accI[oo][j], w_r, xi_[j]); ffma2(accI[oo][j], w_i, xr_[j]);
                }
            }
        }
    }

    // softshrink + store
    #pragma unroll
    for (int oo = 0; oo < 6; oo++) {
        int row = ot * 6 + oo;
        float v[16];
        #pragma unroll
        for (int j = 0; j < 4; j++) {
            unpack2(accR[oo][j], v[2 * j], v[2 * j + 1]);
            unpack2(accI[oo][j], v[8 + 2 * j], v[9 + 2 * j]);
        }
        #pragma unroll
        for (int j = 0; j < 16; j++) {
            float t = fabsf(v[j]) - LAMBDA;
            v[j] = t > 0.f ? copysignf(t, v[j]) : 0.f;
        }
        int m = m0 + lane * 8;
        if (full) {
            *reinterpret_cast<float4*>(SrB + (size_t)row * MP + m)     = make_float4(v[0], v[1], v[2], v[3]);
            *reinterpret_cast<float4*>(SrB + (size_t)row * MP + m + 4) = make_float4(v[4], v[5], v[6], v[7]);
            *reinterpret_cast<float4*>(SiB + (size_t)row * MP + m)     = make_float4(v[8], v[9], v[10], v[11]);
            *reinterpret_cast<float4*>(SiB + (size_t)row * MP + m + 4) = make_float4(v[12], v[13], v[14], v[15]);
        } else {
            #pragma unroll
            for (int j = 0; j < 8; j++) {
                if (m + j < NMODES) {
                    SrB[(size_t)row * MP + m + j] = v[j];
                    SiB[(size_t)row * MP + m + j] = v[8 + j];
                }
            }
        }
    }
}

// ---------------------------------------------------------------------------
extern "C" void kernel_launch(void* const* d_in, const int* in_sizes, int n_in,
                              void* d_out, int out_size) {
    const float* x  = (const float*)d_in[0];
    const float* w1 = (const float*)d_in[1];
    const float* b1 = (const float*)d_in[2];
    const float* w2 = (const float*)d_in[3];
    const float* b2 = (const float*)d_in[4];
    float* y = (float*)d_out;

    const size_t fft_smem = (size_t)(PAIRS_PER_CTA * LSEQ + LSEQ / 2) * sizeof(float2); // 147456
    const size_t mlp_smem = (size_t)(2 * BS * BS + 2 * BS * MT) * sizeof(float);        // 172032

    cudaFuncSetAttribute(fwd_fft_kernel, cudaFuncAttributeMaxDynamicSharedMemorySize, (int)fft_smem);
    cudaFuncSetAttribute(inv_fft_kernel, cudaFuncAttributeMaxDynamicSharedMemorySize, (int)fft_smem);
    cudaFuncSetAttribute(mlp_kernel,     cudaFuncAttributeMaxDynamicSharedMemorySize, (int)mlp_smem);

    fwd_fft_kernel<<<NBATCH * DCH / 8, 1024, fft_smem>>>(x);

    dim3 g((NMODES + MT - 1) / MT, NBLK, NBATCH);
    mlp_kernel<<<g, 256, mlp_smem>>>(w1, b1, w2, b2);

    inv_fft_kernel<<<NBATCH * DCH / 8, 1024, fft_smem>>>(x, y);
}

// round 10
// speedup vs baseline: 1.6790x; 1.0518x over previous
#include <cuda_runtime.h>
#include <math.h>

#define LSEQ   4096
#define DCH    768
#define NBATCH 8
#define NBLK   8
#define BS     96
#define NMODES 2049   // LSEQ/2 + 1
#define MP     2064   // padded mode stride
#define MT     128    // mode tile in MLP kernel
#define LAMBDA 0.01f
#define PAIRS_PER_CTA 4
#define MLP_THREADS 384

// Scratch spectra: (B, D, MP) real and imag
__device__ float g_Sr[(size_t)NBATCH * DCH * MP];
__device__ float g_Si[(size_t)NBATCH * DCH * MP];

extern __shared__ char smem_raw[];

// ---------------- packed f32x2 helpers (FFMA2 path) ----------------
typedef unsigned long long ull;

__device__ __forceinline__ ull bcast2(float v) {
    ull r; asm("mov.b64 %0, {%1, %1};" : "=l"(r) : "f"(v)); return r;
}
__device__ __forceinline__ void unpack2(ull a, float& lo, float& hi) {
    asm("mov.b64 {%0, %1}, %2;" : "=f"(lo), "=f"(hi) : "l"(a));
}
__device__ __forceinline__ void ffma2(ull& d, ull a, ull b) {
    asm("fma.rn.f32x2 %0, %1, %2, %0;" : "+l"(d) : "l"(a), "l"(b));
}

// ---------------------------------------------------------------------------
// Forward FFT (R9-proven): 4 channel-pairs per CTA, 1024 threads.
// Radix-2 Stockham, 12 stages, single buffer per pair (read/sync/write).
// ---------------------------------------------------------------------------
__global__ __launch_bounds__(1024) void fwd_fft_kernel(const float* __restrict__ x) {
    float2* buf = reinterpret_cast<float2*>(smem_raw);       // [4][4096]
    float2* tw  = buf + PAIRS_PER_CTA * LSEQ;                // [2048]
    const int tid = threadIdx.x;
    const int sub = tid >> 8;
    const int st  = tid & 255;
    const int bi  = blockIdx.x;
    const int b   = bi / (DCH / 8);
    const int c0  = (bi % (DCH / 8)) * 8;

    for (int j = tid; j < LSEQ / 2; j += 1024) {
        float sv, cv;
        sincosf(-6.28318530717958647692f * (float)j / (float)LSEQ, &sv, &cv);
        tw[j] = make_float2(cv, sv);
    }
    const float* xs = x + (size_t)b * LSEQ * DCH + c0;
    for (int i = tid; i < LSEQ * 2; i += 1024) {
        int l = i >> 1, h = i & 1;
        float4 v = *reinterpret_cast<const float4*>(xs + (size_t)l * DCH + h * 4);
        buf[(2 * h)     * LSEQ + l] = make_float2(v.x, v.y);
        buf[(2 * h + 1) * LSEQ + l] = make_float2(v.z, v.w);
    }
    __syncthreads();

    float2* bp = buf + sub * LSEQ;
    for (int ls = 0; ls < 12; ls++) {
        const int s = 1 << ls;
        float2 a[8], c[8];
        #pragma unroll
        for (int k = 0; k < 8; k++) {
            int bt = st + (k << 8);
            a[k] = bp[bt];
            c[k] = bp[bt + 2048];
        }
        __syncthreads();
        #pragma unroll
        for (int k = 0; k < 8; k++) {
            int bt = st + (k << 8);
            int r  = bt & ~(s - 1);
            float2 w = tw[r];
            float dx = a[k].x - c[k].x, dy = a[k].y - c[k].y;
            int o = bt + r;
            bp[o]     = make_float2(a[k].x + c[k].x, a[k].y + c[k].y);
            bp[o + s] = make_float2(dx * w.x - dy * w.y, dx * w.y + dy * w.x);
        }
        __syncthreads();
    }
    const int d0 = c0 + 2 * sub;
    const float scale = 0.5f / 64.0f;
    float* SrB = g_Sr + ((size_t)b * DCH + d0) * MP;
    float* SiB = g_Si + ((size_t)b * DCH + d0) * MP;
    for (int k = st; k < NMODES; k += 256) {
        float2 z1 = bp[k];
        float2 z2 = bp[(LSEQ - k) & (LSEQ - 1)];
        SrB[k]      = (z1.x + z2.x) * scale;
        SiB[k]      = (z1.y - z2.y) * scale;
        SrB[MP + k] = (z1.y + z2.y) * scale;
        SiB[MP + k] = (z2.x - z1.x) * scale;
    }
}

// ---------------------------------------------------------------------------
// Inverse FFT (R9-proven): same structure, conjugate twiddles, residual add.
// ---------------------------------------------------------------------------
__global__ __launch_bounds__(1024) void inv_fft_kernel(const float* __restrict__ x,
                                                       float* __restrict__ y) {
    float2* buf = reinterpret_cast<float2*>(smem_raw);
    float2* tw  = buf + PAIRS_PER_CTA * LSEQ;
    const int tid = threadIdx.x;
    const int sub = tid >> 8;
    const int st  = tid & 255;
    const int bi  = blockIdx.x;
    const int b   = bi / (DCH / 8);
    const int c0  = (bi % (DCH / 8)) * 8;
    const int d0  = c0 + 2 * sub;

    for (int j = tid; j < LSEQ / 2; j += 1024) {
        float sv, cv;
        sincosf(6.28318530717958647692f * (float)j / (float)LSEQ, &sv, &cv);
        tw[j] = make_float2(cv, sv);
    }
    float2* bp = buf + sub * LSEQ;
    const float* SrB = g_Sr + ((size_t)b * DCH + d0) * MP;
    const float* SiB = g_Si + ((size_t)b * DCH + d0) * MP;
    for (int k = st; k < NMODES; k += 256) {
        float ar  = SrB[k],      ai  = SiB[k];
        float br  = SrB[MP + k], bi_ = SiB[MP + k];
        if (k == 0 || k == LSEQ / 2) { ai = 0.0f; bi_ = 0.0f; }
        bp[k] = make_float2(ar - bi_, ai + br);
        if (k > 0 && k < LSEQ / 2)
            bp[LSEQ - k] = make_float2(ar + bi_, br - ai);
    }
    __syncthreads();

    for (int ls = 0; ls < 12; ls++) {
        const int s = 1 << ls;
        float2 a[8], c[8];
        #pragma unroll
        for (int k = 0; k < 8; k++) {
            int bt = st + (k << 8);
            a[k] = bp[bt];
            c[k] = bp[bt + 2048];
        }
        __syncthreads();
        #pragma unroll
        for (int k = 0; k < 8; k++) {
            int bt = st + (k << 8);
            int r  = bt & ~(s - 1);
            float2 w = tw[r];
            float dx = a[k].x - c[k].x, dy = a[k].y - c[k].y;
            int o = bt + r;
            bp[o]     = make_float2(a[k].x + c[k].x, a[k].y + c[k].y);
            bp[o + s] = make_float2(dx * w.x - dy * w.y, dx * w.y + dy * w.x);
        }
        __syncthreads();
    }
    const float sc = 1.0f / 64.0f;
    const float* xs = x + (size_t)b * LSEQ * DCH + c0;
    float*       ys = y + (size_t)b * LSEQ * DCH + c0;
    for (int i = tid; i < LSEQ * 2; i += 1024) {
        int l = i >> 1, h = i & 1;
        float2 u  = buf[(2 * h)     * LSEQ + l];
        float2 v2 = buf[(2 * h + 1) * LSEQ + l];
        float4 xv = *reinterpret_cast<const float4*>(xs + (size_t)l * DCH + h * 4);
        float4 out = make_float4(xv.x + u.x * sc,  xv.y + u.y * sc,
                                 xv.z + v2.x * sc, xv.w + v2.y * sc);
        *reinterpret_cast<float4*>(ys + (size_t)l * DCH + h * 4) = out;
    }
}

// ---------------------------------------------------------------------------
// Per-mode complex block-diagonal MLP, packed f32x2 FMA, 384 threads.
// Grid: (17 mode-tiles, 8 blocks, 8 batch). 12 warps/CTA (3/SMSP).
// lane = tid&15 -> modes lane*8..+7 (4 pairs); og = tid>>4 (0..23) ->
// outputs og*4..+3. Per K-step: 64 FFMA2 + 6 LDS.128 + 8 bcast + 4 XOR.
// Smem: W (72KB) + X/O1 (96KB) = 168KB, 1 CTA/SM.
// ---------------------------------------------------------------------------
__global__ __launch_bounds__(MLP_THREADS) void mlp_kernel(const float* __restrict__ w1,
                                                          const float* __restrict__ b1,
                                                          const float* __restrict__ w2,
                                                          const float* __restrict__ b2) {
    float* Wr = reinterpret_cast<float*>(smem_raw);    // [96][96]
    float* Wi = Wr + BS * BS;
    float* Xr = Wi + BS * BS;                          // [96][128], reused for O1
    float* Xi = Xr + BS * MT;

    const int tid  = threadIdx.x;
    const int n    = blockIdx.y;
    const int b    = blockIdx.z;
    const int m0   = blockIdx.x * MT;
    const int lane = tid & 15;
    const int og   = tid >> 4;          // 0..23
    const bool full = (m0 + MT <= NMODES);

    // stage W1 (layout w1[c][n][i][o])
    {
        const float4* w1r4 = reinterpret_cast<const float4*>(w1 + (size_t)n * BS * BS);
        const float4* w1i4 = reinterpret_cast<const float4*>(w1 + (size_t)(NBLK + n) * BS * BS);
        for (int t = tid; t < BS * BS / 4; t += MLP_THREADS) {
            reinterpret_cast<float4*>(Wr)[t] = w1r4[t];
            reinterpret_cast<float4*>(Wi)[t] = w1i4[t];
        }
    }
    float* SrB = g_Sr + ((size_t)b * DCH + n * BS) * MP;
    float* SiB = g_Si + ((size_t)b * DCH + n * BS) * MP;
    for (int t = tid; t < BS * (MT / 4); t += MLP_THREADS) {
        int i = t >> 5, c = t & 31;
        int m = m0 + c * 4;
        float4 vr, vi;
        if (full) {
            vr = *reinterpret_cast<const float4*>(SrB + (size_t)i * MP + m);
            vi = *reinterpret_cast<const float4*>(SiB + (size_t)i * MP + m);
        } else {
            vr = make_float4(0.f, 0.f, 0.f, 0.f);
            vi = make_float4(0.f, 0.f, 0.f, 0.f);
            #pragma unroll
            for (int j = 0; j < 4; j++) {
                if (m + j < NMODES) {
                    (&vr.x)[j] = SrB[(size_t)i * MP + m + j];
                    (&vi.x)[j] = SiB[(size_t)i * MP + m + j];
                }
            }
        }
        *reinterpret_cast<float4*>(Xr + i * MT + c * 4) = vr;
        *reinterpret_cast<float4*>(Xi + i * MT + c * 4) = vi;
    }
    __syncthreads();

    const ull SGN2 = 0x8000000080000000ULL;

    // ---------------- layer 1 ----------------
    ull accR[4][4], accI[4][4];   // [oo][mode-pair]
    {
        const float* b1r = b1 + (size_t)n * BS + og * 4;
        const float* b1i = b1 + (size_t)(NBLK + n) * BS + og * 4;
        #pragma unroll
        for (int oo = 0; oo < 4; oo++) {
            ull vr = bcast2(b1r[oo]), vi = bcast2(b1i[oo]);
            #pragma unroll
            for (int j = 0; j < 4; j++) { accR[oo][j] = vr; accI[oo][j] = vi; }
        }
    }
    {
        const float* xrp = Xr + lane * 8;
        const float* xip = Xi + lane * 8;
        const float* wrp = Wr + og * 4;
        const float* wip = Wi + og * 4;
        for (int i = 0; i < BS; i++) {
            ulonglong2 xra = *reinterpret_cast<const ulonglong2*>(xrp + i * MT);
            ulonglong2 xrb = *reinterpret_cast<const ulonglong2*>(xrp + i * MT + 4);
            ulonglong2 xia = *reinterpret_cast<const ulonglong2*>(xip + i * MT);
            ulonglong2 xib = *reinterpret_cast<const ulonglong2*>(xip + i * MT + 4);
            ull xr_[4] = {xra.x, xra.y, xrb.x, xrb.y};
            ull xi_[4] = {xia.x, xia.y, xib.x, xib.y};
            ull nxi[4] = {xia.x ^ SGN2, xia.y ^ SGN2, xib.x ^ SGN2, xib.y ^ SGN2};
            float4 wr4 = *reinterpret_cast<const float4*>(wrp + i * BS);
            float4 wi4 = *reinterpret_cast<const float4*>(wip + i * BS);
            const float* wrv = &wr4.x;
            const float* wiv = &wi4.x;
            #pragma unroll
            for (int oo = 0; oo < 4; oo++) {
                ull w_r = bcast2(wrv[oo]);
                ull w_i = bcast2(wiv[oo]);
                #pragma unroll
                for (int j = 0; j < 4; j++) {
                    ffma2(accR[oo][j], w_r, xr_[j]); ffma2(accR[oo][j], w_i, nxi[j]);
                    ffma2(accI[oo][j], w_r, xi_[j]); ffma2(accI[oo][j], w_i, xr_[j]);
                }
            }
        }
    }
    __syncthreads();   // all X / W1 reads done

    // relu -> O1 (into X buffer); stage W2
    #pragma unroll
    for (int oo = 0; oo < 4; oo++) {
        int row = og * 4 + oo;
        float r[8], im[8];
        #pragma unroll
        for (int j = 0; j < 4; j++) {
            unpack2(accR[oo][j], r[2 * j], r[2 * j + 1]);
            unpack2(accI[oo][j], im[2 * j], im[2 * j + 1]);
        }
        *reinterpret_cast<float4*>(Xr + row * MT + lane * 8) =
            make_float4(fmaxf(r[0], 0.f), fmaxf(r[1], 0.f), fmaxf(r[2], 0.f), fmaxf(r[3], 0.f));
        *reinterpret_cast<float4*>(Xr + row * MT + lane * 8 + 4) =
            make_float4(fmaxf(r[4], 0.f), fmaxf(r[5], 0.f), fmaxf(r[6], 0.f), fmaxf(r[7], 0.f));
        *reinterpret_cast<float4*>(Xi + row * MT + lane * 8) =
            make_float4(fmaxf(im[0], 0.f), fmaxf(im[1], 0.f), fmaxf(im[2], 0.f), fmaxf(im[3], 0.f));
        *reinterpret_cast<float4*>(Xi + row * MT + lane * 8 + 4) =
            make_float4(fmaxf(im[4], 0.f), fmaxf(im[5], 0.f), fmaxf(im[6], 0.f), fmaxf(im[7], 0.f));
    }
    {
        const float4* w2r4 = reinterpret_cast<const float4*>(w2 + (size_t)n * BS * BS);
        const float4* w2i4 = reinterpret_cast<const float4*>(w2 + (size_t)(NBLK + n) * BS * BS);
        for (int t = tid; t < BS * BS / 4; t += MLP_THREADS) {
            reinterpret_cast<float4*>(Wr)[t] = w2r4[t];
            reinterpret_cast<float4*>(Wi)[t] = w2i4[t];
        }
    }
    __syncthreads();

    // ---------------- layer 2 ----------------
    {
        const float* b2r = b2 + (size_t)n * BS + og * 4;
        const float* b2i = b2 + (size_t)(NBLK + n) * BS + og * 4;
        #pragma unroll
        for (int oo = 0; oo < 4; oo++) {
            ull vr = bcast2(b2r[oo]), vi = bcast2(b2i[oo]);
            #pragma unroll
            for (int j = 0; j < 4; j++) { accR[oo][j] = vr; accI[oo][j] = vi; }
        }
    }
    {
        const float* xrp = Xr + lane * 8;
        const float* xip = Xi + lane * 8;
        const float* wrp = Wr + og * 4;
        const float* wip = Wi + og * 4;
        for (int o = 0; o < BS; o++) {
            ulonglong2 xra = *reinterpret_cast<const ulonglong2*>(xrp + o * MT);
            ulonglong2 xrb = *reinterpret_cast<const ulonglong2*>(xrp + o * MT + 4);
            ulonglong2 xia = *reinterpret_cast<const ulonglong2*>(xip + o * MT);
            ulonglong2 xib = *reinterpret_cast<const ulonglong2*>(xip + o * MT + 4);
            ull xr_[4] = {xra.x, xra.y, xrb.x, xrb.y};
            ull xi_[4] = {xia.x, xia.y, xib.x, xib.y};
            ull nxi[4] = {xia.x ^ SGN2, xia.y ^ SGN2, xib.x ^ SGN2, xib.y ^ SGN2};
            float4 wr4 = *reinterpret_cast<const float4*>(wrp + o * BS);
            float4 wi4 = *reinterpret_cast<const float4*>(wip + o * BS);
            const float* wrv = &wr4.x;
            const float* wiv = &wi4.x;
            #pragma unroll
            for (int oo = 0; oo < 4; oo++) {
                ull w_r = bcast2(wrv[oo]);
                ull w_i = bcast2(wiv[oo]);
                #pragma unroll
                for (int j = 0; j < 4; j++) {
                    ffma2(accR[oo][j], w_r, xr_[j]); ffma2(accR[oo][j], w_i, nxi[j]);
                    ffma2(accI[oo][j], w_r, xi_[j]); ffma2(accI[oo][j], w_i, xr_[j]);
                }
            }
        }
    }

    // softshrink + store
    #pragma unroll
    for (int oo = 0; oo < 4; oo++) {
        int row = og * 4 + oo;
        float v[16];
        #pragma unroll
        for (int j = 0; j < 4; j++) {
            unpack2(accR[oo][j], v[2 * j], v[2 * j + 1]);
            unpack2(accI[oo][j], v[8 + 2 * j], v[9 + 2 * j]);
        }
        #pragma unroll
        for (int j = 0; j < 16; j++) {
            float t = fabsf(v[j]) - LAMBDA;
            v[j] = t > 0.f ? copysignf(t, v[j]) : 0.f;
        }
        int m = m0 + lane * 8;
        if (full) {
            *reinterpret_cast<float4*>(SrB + (size_t)row * MP + m)     = make_float4(v[0], v[1], v[2], v[3]);
            *reinterpret_cast<float4*>(SrB + (size_t)row * MP + m + 4) = make_float4(v[4], v[5], v[6], v[7]);
            *reinterpret_cast<float4*>(SiB + (size_t)row * MP + m)     = make_float4(v[8], v[9], v[10], v[11]);
            *reinterpret_cast<float4*>(SiB + (size_t)row * MP + m + 4) = make_float4(v[12], v[13], v[14], v[15]);
        } else {
            #pragma unroll
            for (int j = 0; j < 8; j++) {
                if (m + j < NMODES) {
                    SrB[(size_t)row * MP + m + j] = v[j];
                    SiB[(size_t)row * MP + m + j] = v[8 + j];
                }
            }
        }
    }
}

// ---------------------------------------------------------------------------
extern "C" void kernel_launch(void* const* d_in, const int* in_sizes, int n_in,
                              void* d_out, int out_size) {
    const float* x  = (const float*)d_in[0];
    const float* w1 = (const float*)d_in[1];
    const float* b1 = (const float*)d_in[2];
    const float* w2 = (const float*)d_in[3];
    const float* b2 = (const float*)d_in[4];
    float* y = (float*)d_out;

    const size_t fft_smem = (size_t)(PAIRS_PER_CTA * LSEQ + LSEQ / 2) * sizeof(float2); // 147456
    const size_t mlp_smem = (size_t)(2 * BS * BS + 2 * BS * MT) * sizeof(float);        // 172032

    cudaFuncSetAttribute(fwd_fft_kernel, cudaFuncAttributeMaxDynamicSharedMemorySize, (int)fft_smem);
    cudaFuncSetAttribute(inv_fft_kernel, cudaFuncAttributeMaxDynamicSharedMemorySize, (int)fft_smem);
    cudaFuncSetAttribute(mlp_kernel,     cudaFuncAttributeMaxDynamicSharedMemorySize, (int)mlp_smem);

    fwd_fft_kernel<<<NBATCH * DCH / 8, 1024, fft_smem>>>(x);

    dim3 g((NMODES + MT - 1) / MT, NBLK, NBATCH);
    mlp_kernel<<<g, MLP_THREADS, mlp_smem>>>(w1, b1, w2, b2);

    inv_fft_kernel<<<NBATCH * DCH / 8, 1024, fft_smem>>>(x, y);
}